// round 15
// baseline (speedup 1.0000x reference)
#include <cuda_runtime.h>
#include <cuda_bf16.h>
#include <cuda_fp16.h>
#include <cstdint>

#define N_NODES 50000
#define N_EDGES 800000
#define IN_DIM  256
#define HC      128   // HEADS * OUT_DIM
#define HEADS   4
#define NEG_SLOPE 0.2f
#define LN_EPS  1e-5f

// Scratch (static device globals; no allocation at runtime)
__device__ __half g_hf[(size_t)N_NODES * HC];    // transformed features, fp16
__device__ float g_as[N_NODES * HEADS];          // alpha_src per node/head
__device__ float g_ad[N_NODES * HEADS];          // alpha_dst per node/head
// W pre-split (bf16 hi/lo), transposed to [n][k]
__device__ __nv_bfloat16 g_Whi[HC * IN_DIM];
__device__ __nv_bfloat16 g_Wlo[HC * IN_DIM];
// CSR-by-dst scratch
__device__ int   g_deg[N_NODES];
__device__ int   g_cur[N_NODES];
__device__ int   g_row[N_NODES + 1];
__device__ int   g_col[N_EDGES];
__device__ int   g_scan[50176];
__device__ int   g_poff[64];

// ---------------------------------------------------------------------------
// Prep (stream 0): split W into bf16 hi/lo transposed [n][k].
// ---------------------------------------------------------------------------
__global__ __launch_bounds__(256) void prep_k(const float* __restrict__ W) {
    int i = blockIdx.x * 256 + threadIdx.x;
    if (i < IN_DIM * HC) {
        int k = i >> 7, n = i & 127;
        float v = W[i];
        __nv_bfloat16 h = __float2bfloat16(v);
        float r = v - __bfloat162float(h);
        g_Whi[n * IN_DIM + k] = h;
        g_Wlo[n * IN_DIM + k] = __float2bfloat16(r);
    }
}

// CSR branch start: zero counters
__global__ __launch_bounds__(256) void zero_k() {
    int i = blockIdx.x * 256 + threadIdx.x;
    if (i < N_NODES) { g_deg[i] = 0; g_cur[i] = 0; }
}

#define MMA_BF16(D, A0, A1, A2, A3, B0, B1)                                   \
    asm volatile(                                                             \
        "mma.sync.aligned.m16n8k16.row.col.f32.bf16.bf16.f32 "                \
        "{%0,%1,%2,%3},{%4,%5,%6,%7},{%8,%9},{%0,%1,%2,%3};"                  \
        : "+f"(D[0]), "+f"(D[1]), "+f"(D[2]), "+f"(D[3])                      \
        : "r"(A0), "r"(A1), "r"(A2), "r"(A3), "r"(B0), "r"(B1))

#define LDSM_X4(R0, R1, R2, R3, ADDR)                                         \
    asm volatile("ldmatrix.sync.aligned.m8n8.x4.shared.b16 {%0,%1,%2,%3}, [%4];" \
                 : "=r"(R0), "=r"(R1), "=r"(R2), "=r"(R3) : "r"(ADDR))

#define CP16(dst_u32, src_ptr)                                                \
    asm volatile("cp.async.cg.shared.global [%0], [%1], 16;" ::               \
                 "r"(dst_u32), "l"(src_ptr))
#define CP_COMMIT() asm volatile("cp.async.commit_group;")
#define CP_WAIT0()  asm volatile("cp.async.wait_group 0;")

// stage layout (bytes): Xh[64][40] | Xl[64][40] | Wh[128][40] | Wl[128][40]
#define XH_OFF 0
#define XL_OFF 5120
#define WH_OFF 10240
#define WL_OFF 20480
#define STG_BYTES 30720

// ---------------------------------------------------------------------------
// K1: h = x@W via 3-term bf16-split mma, double-buffered pipeline.
// Tile M=64, N=128, K-chunk 32; 8 warps: warp tile m16 (wid&3) x n64 (wid>>2).
// ldmatrix fragment loads keep the mainloop MMA-bound (10 LDSM : 24 MMA / ks).
// 3 CTAs/SM (60 KB smem) -> 782 CTAs / 444 slots = 1.76 waves of half tiles.
// ---------------------------------------------------------------------------
__global__ __launch_bounds__(256, 3) void gemm_mma_k(const float* __restrict__ x,
                                                     const float* __restrict__ att_src,
                                                     const float* __restrict__ att_dst) {
    extern __shared__ __align__(16) char sm_raw[];

    const int tid  = threadIdx.x;
    const int wid  = tid >> 5;
    const int lane = tid & 31;
    const int g    = lane >> 2;
    const int tig  = lane & 3;
    const int wm   = (wid & 3) * 16;
    const int wn   = (wid >> 2) * 64;
    const int nb   = blockIdx.x * 64;

    const uint32_t smem_u32 = (uint32_t)__cvta_generic_to_shared(sm_raw);

    // ldmatrix per-lane byte offsets (within a stage, excluding ks*2)
    const int a_off = (((wm + (lane & 7) + ((lane >> 3) & 1) * 8) * 40)
                       + ((lane >> 4) & 1) * 8) * 2;
    int b_off[4];
#pragma unroll
    for (int p = 0; p < 4; p++)
        b_off[p] = (((wn + p * 16 + (lane & 7) + ((lane >> 4) & 1) * 8) * 40)
                    + ((lane >> 3) & 1) * 8) * 2;

    // X loads: 64 rows x 32 k fp32 = 512 float4, 2 per thread
    const float* xsrc[2];
    int xoff[2];
#pragma unroll
    for (int i = 0; i < 2; i++) {
        int idx = tid + i * 256;
        int row = idx >> 3, q = idx & 7;
        int gn  = nb + row; if (gn > N_NODES - 1) gn = N_NODES - 1;
        xoff[i] = row * 40 + q * 4;
        xsrc[i] = x + (size_t)gn * IN_DIM + q * 4;
    }
    // W cp.async: 128 rows x 32 k bf16 per h/l; 2 CP16 each per thread
    int wrow[2], wq[2];
#pragma unroll
    for (int i = 0; i < 2; i++) {
        int idx = tid + i * 256;
        wrow[i] = idx >> 2; wq[i] = idx & 3;
    }

    float d[8][4];
#pragma unroll
    for (int nt = 0; nt < 8; nt++)
#pragma unroll
        for (int c = 0; c < 4; c++) d[nt][c] = 0.f;

    float4 xs[2];

    // --- prologue: chunk 0 ---
    {
        char* st0 = sm_raw;
#pragma unroll
        for (int i = 0; i < 2; i++) {
            uint32_t dh = smem_u32 + WH_OFF + (wrow[i] * 40 + wq[i] * 8) * 2;
            uint32_t dl = smem_u32 + WL_OFF + (wrow[i] * 40 + wq[i] * 8) * 2;
            CP16(dh, g_Whi + (size_t)wrow[i] * IN_DIM + wq[i] * 8);
            CP16(dl, g_Wlo + (size_t)wrow[i] * IN_DIM + wq[i] * 8);
        }
        CP_COMMIT();
#pragma unroll
        for (int i = 0; i < 2; i++) xs[i] = *(const float4*)(xsrc[i]);
        __nv_bfloat16* Xh = (__nv_bfloat16*)(st0 + XH_OFF);
        __nv_bfloat16* Xl = (__nv_bfloat16*)(st0 + XL_OFF);
#pragma unroll
        for (int i = 0; i < 2; i++) {
            float4 v = xs[i];
            __nv_bfloat162 h01 = make_bfloat162(__float2bfloat16(v.x), __float2bfloat16(v.y));
            __nv_bfloat162 h23 = make_bfloat162(__float2bfloat16(v.z), __float2bfloat16(v.w));
            __nv_bfloat162 l01 = make_bfloat162(
                __float2bfloat16(v.x - __bfloat162float(h01.x)),
                __float2bfloat16(v.y - __bfloat162float(h01.y)));
            __nv_bfloat162 l23 = make_bfloat162(
                __float2bfloat16(v.z - __bfloat162float(h23.x)),
                __float2bfloat16(v.w - __bfloat162float(h23.y)));
            *(__nv_bfloat162*)&Xh[xoff[i]]     = h01;
            *(__nv_bfloat162*)&Xh[xoff[i] + 2] = h23;
            *(__nv_bfloat162*)&Xl[xoff[i]]     = l01;
            *(__nv_bfloat162*)&Xl[xoff[i] + 2] = l23;
        }
        CP_WAIT0();
        __syncthreads();
    }

    for (int c = 0; c < 8; c++) {
        const int cur = c & 1;
        const int nxt = cur ^ 1;
        char* bn = sm_raw + nxt * STG_BYTES;
        const uint32_t base = smem_u32 + cur * STG_BYTES;

        if (c < 7) {
            const int kc = (c + 1) * 32;
#pragma unroll
            for (int i = 0; i < 2; i++) {
                uint32_t dh = smem_u32 + nxt * STG_BYTES + WH_OFF + (wrow[i] * 40 + wq[i] * 8) * 2;
                uint32_t dl = smem_u32 + nxt * STG_BYTES + WL_OFF + (wrow[i] * 40 + wq[i] * 8) * 2;
                CP16(dh, g_Whi + (size_t)wrow[i] * IN_DIM + kc + wq[i] * 8);
                CP16(dl, g_Wlo + (size_t)wrow[i] * IN_DIM + kc + wq[i] * 8);
            }
            CP_COMMIT();
#pragma unroll
            for (int i = 0; i < 2; i++) xs[i] = *(const float4*)(xsrc[i] + kc);
        }

        // --- compute on current stage (ldmatrix fragment loads) ---
#pragma unroll
        for (int ks = 0; ks < 32; ks += 16) {
            uint32_t ah[4], al[4];
            LDSM_X4(ah[0], ah[1], ah[2], ah[3], base + XH_OFF + a_off + ks * 2);
            LDSM_X4(al[0], al[1], al[2], al[3], base + XL_OFF + a_off + ks * 2);
#pragma unroll
            for (int p = 0; p < 4; p++) {
                uint32_t bh[4], bl[4];
                LDSM_X4(bh[0], bh[1], bh[2], bh[3], base + WH_OFF + b_off[p] + ks * 2);
                LDSM_X4(bl[0], bl[1], bl[2], bl[3], base + WL_OFF + b_off[p] + ks * 2);
#pragma unroll
                for (int j = 0; j < 2; j++) {
                    int nt = 2 * p + j;
                    uint32_t bh0 = bh[2 * j], bh1 = bh[2 * j + 1];
                    uint32_t bl0 = bl[2 * j], bl1 = bl[2 * j + 1];
                    MMA_BF16(d[nt], ah[0], ah[1], ah[2], ah[3], bh0, bh1);
                    MMA_BF16(d[nt], ah[0], ah[1], ah[2], ah[3], bl0, bl1);
                    MMA_BF16(d[nt], al[0], al[1], al[2], al[3], bh0, bh1);
                }
            }
        }

        if (c < 7) {
            __nv_bfloat16* Xhn = (__nv_bfloat16*)(bn + XH_OFF);
            __nv_bfloat16* Xln = (__nv_bfloat16*)(bn + XL_OFF);
#pragma unroll
            for (int i = 0; i < 2; i++) {
                float4 v = xs[i];
                __nv_bfloat162 h01 = make_bfloat162(__float2bfloat16(v.x), __float2bfloat16(v.y));
                __nv_bfloat162 h23 = make_bfloat162(__float2bfloat16(v.z), __float2bfloat16(v.w));
                __nv_bfloat162 l01 = make_bfloat162(
                    __float2bfloat16(v.x - __bfloat162float(h01.x)),
                    __float2bfloat16(v.y - __bfloat162float(h01.y)));
                __nv_bfloat162 l23 = make_bfloat162(
                    __float2bfloat16(v.z - __bfloat162float(h23.x)),
                    __float2bfloat16(v.w - __bfloat162float(h23.y)));
                *(__nv_bfloat162*)&Xhn[xoff[i]]     = h01;
                *(__nv_bfloat162*)&Xhn[xoff[i] + 2] = h23;
                *(__nv_bfloat162*)&Xln[xoff[i]]     = l01;
                *(__nv_bfloat162*)&Xln[xoff[i] + 2] = l23;
            }
            CP_WAIT0();
        }
        __syncthreads();
    }

    // ---- epilogue: store h (fp16) + attention logits (fp32) ----
    // rows n0 = nb+wm+g, n1 = n0+8; cols wn + nt*8 + 2*tig (+1)
    const int head0 = wn >> 5;
    float psl[2], pdl[2], psh[2], pdh[2];
#pragma unroll
    for (int hh = 0; hh < 2; hh++) { psl[hh]=pdl[hh]=psh[hh]=pdh[hh]=0.f; }

#pragma unroll
    for (int nt = 0; nt < 8; nt++) {
        int c0 = wn + nt * 8 + 2 * tig;
        int hh = nt >> 2;
        float as0 = __ldg(att_src + c0), as1 = __ldg(att_src + c0 + 1);
        float ad0 = __ldg(att_dst + c0), ad1 = __ldg(att_dst + c0 + 1);
        psl[hh] += d[nt][0] * as0 + d[nt][1] * as1;
        pdl[hh] += d[nt][0] * ad0 + d[nt][1] * ad1;
        psh[hh] += d[nt][2] * as0 + d[nt][3] * as1;
        pdh[hh] += d[nt][2] * ad0 + d[nt][3] * ad1;
    }
#pragma unroll
    for (int hh = 0; hh < 2; hh++)
#pragma unroll
        for (int o = 1; o <= 2; o <<= 1) {
            psl[hh] += __shfl_xor_sync(0xffffffffu, psl[hh], o);
            pdl[hh] += __shfl_xor_sync(0xffffffffu, pdl[hh], o);
            psh[hh] += __shfl_xor_sync(0xffffffffu, psh[hh], o);
            pdh[hh] += __shfl_xor_sync(0xffffffffu, pdh[hh], o);
        }

    const int n0 = nb + wm + g;
    const int n1 = n0 + 8;
    if (n0 < N_NODES) {
#pragma unroll
        for (int nt = 0; nt < 8; nt++)
            *(__half2*)(g_hf + (size_t)n0 * HC + wn + nt * 8 + 2 * tig) =
                __floats2half2_rn(d[nt][0], d[nt][1]);
        if (tig == 0)
#pragma unroll
            for (int hh = 0; hh < 2; hh++) {
                g_as[n0 * HEADS + head0 + hh] = psl[hh];
                g_ad[n0 * HEADS + head0 + hh] = pdl[hh];
            }
    }
    if (n1 < N_NODES) {
#pragma unroll
        for (int nt = 0; nt < 8; nt++)
            *(__half2*)(g_hf + (size_t)n1 * HC + wn + nt * 8 + 2 * tig) =
                __floats2half2_rn(d[nt][2], d[nt][3]);
        if (tig == 0)
#pragma unroll
            for (int hh = 0; hh < 2; hh++) {
                g_as[n1 * HEADS + head0 + hh] = psh[hh];
                g_ad[n1 * HEADS + head0 + hh] = pdh[hh];
            }
    }
}

// ---------------------------------------------------------------------------
// CSR build: hist -> scan (2-level, warp-shuffle) -> fill
// ---------------------------------------------------------------------------
__global__ __launch_bounds__(256) void hist_k(const int* __restrict__ ei) {
    int e = blockIdx.x * 256 + threadIdx.x;
    if (e < N_EDGES) atomicAdd(&g_deg[__ldg(ei + N_EDGES + e)], 1);
}

__global__ __launch_bounds__(1024) void scan1_k() {
    __shared__ int wsum[32];
    int tid = threadIdx.x, lane = tid & 31, wid = tid >> 5;
    int i = blockIdx.x * 1024 + tid;
    int v = (i < N_NODES) ? g_deg[i] : 0;
    int s = v;
#pragma unroll
    for (int o = 1; o < 32; o <<= 1) {
        int t = __shfl_up_sync(0xffffffffu, s, o);
        if (lane >= o) s += t;
    }
    if (lane == 31) wsum[wid] = s;
    __syncthreads();
    if (wid == 0) {
        int t = wsum[lane];
#pragma unroll
        for (int o = 1; o < 32; o <<= 1) {
            int u = __shfl_up_sync(0xffffffffu, t, o);
            if (lane >= o) t += u;
        }
        wsum[lane] = t;
    }
    __syncthreads();
    if (wid > 0) s += wsum[wid - 1];
    g_scan[i] = s;
    if (tid == 1023) g_poff[blockIdx.x] = s;
}

__global__ __launch_bounds__(64) void scan2_k(int nblk) {
    __shared__ int s[64];
    int tid = threadIdx.x;
    s[tid] = (tid < nblk) ? g_poff[tid] : 0;
    __syncthreads();
    if (tid == 0) {
        int run = 0;
        for (int b = 0; b < nblk; b++) { int t = s[b]; s[b] = run; run += t; }
    }
    __syncthreads();
    if (tid < nblk) g_poff[tid] = s[tid];
}

__global__ __launch_bounds__(256) void scan3_k() {
    int i = blockIdx.x * 256 + threadIdx.x;
    if (i < N_NODES) g_row[i + 1] = g_scan[i] + g_poff[i >> 10];
    if (i == 0) g_row[0] = 0;
}

__global__ __launch_bounds__(256) void fill_k(const int* __restrict__ ei) {
    int e = blockIdx.x * 256 + threadIdx.x;
    if (e >= N_EDGES) return;
    int s = __ldg(ei + e);
    int d = __ldg(ei + N_EDGES + e);
    int pos = g_row[d] + atomicAdd(&g_cur[d], 1);
    g_col[pos] = s;
}

// ---------------------------------------------------------------------------
// Aggregation (fp16 gather, 8-way MLP unroll) fused with LayerNorm + ELU.
// One warp per dst node; lane owns 4 channels (one uint2 = 2 half2).
// ---------------------------------------------------------------------------
__global__ __launch_bounds__(256) void aggr_k(const float* __restrict__ bias,
                                              const float* __restrict__ gamma,
                                              const float* __restrict__ beta,
                                              float* __restrict__ out) {
    int gt   = blockIdx.x * 256 + threadIdx.x;
    int n    = gt >> 5;
    int lane = gt & 31;
    if (n >= N_NODES) return;
    int head = lane >> 3;

    float ad_n = __ldg(g_ad + n * HEADS + head);

    // self-loop initializes the accumulator
    float as_s = __ldg(g_as + n * HEADS + head);
    float z    = as_s + ad_n;
    float w    = __expf(z > 0.f ? z : NEG_SLOPE * z);
    uint2 u0i  = __ldg((const uint2*)(g_hf + (size_t)n * HC) + lane);
    float2 f01 = __half22float2(*(__half2*)&u0i.x);
    float2 f23 = __half22float2(*(__half2*)&u0i.y);
    float a0 = w * f01.x, a1 = w * f01.y, a2 = w * f23.x, a3 = w * f23.y;
    float den = w;

    const int e0 = __ldg(g_row + n), e1 = __ldg(g_row + n + 1);
    int i = e0;

    // --- unrolled by 8: batch independent loads to raise MLP ---
#pragma unroll 1
    for (; i + 8 <= e1; i += 8) {
        int sx[8];
        uint2 ux[8];
        float asx[8];
#pragma unroll
        for (int j = 0; j < 8; j++) sx[j] = __ldg(g_col + i + j);
#pragma unroll
        for (int j = 0; j < 8; j++)
            ux[j] = __ldg((const uint2*)(g_hf + (size_t)sx[j] * HC) + lane);
#pragma unroll
        for (int j = 0; j < 8; j++) asx[j] = __ldg(g_as + sx[j] * HEADS + head);

#pragma unroll
        for (int j = 0; j < 8; j++) {
            float zz = asx[j] + ad_n;
            float ww = __expf(zz > 0.f ? zz : NEG_SLOPE * zz);
            den += ww;
            float2 p  = __half22float2(*(__half2*)&ux[j].x);
            float2 q2 = __half22float2(*(__half2*)&ux[j].y);
            a0 = fmaf(ww, p.x, a0);  a1 = fmaf(ww, p.y, a1);
            a2 = fmaf(ww, q2.x, a2); a3 = fmaf(ww, q2.y, a3);
        }
    }
    // --- tail ---
#pragma unroll 1
    for (; i < e1; i++) {
        int s = __ldg(g_col + i);
        uint2 u  = __ldg((const uint2*)(g_hf + (size_t)s * HC) + lane);
        float as = __ldg(g_as + s * HEADS + head);
        float zz = as + ad_n;
        float ww = __expf(zz > 0.f ? zz : NEG_SLOPE * zz);
        float2 h01 = __half22float2(*(__half2*)&u.x);
        float2 h23 = __half22float2(*(__half2*)&u.y);
        a0 = fmaf(ww, h01.x, a0);
        a1 = fmaf(ww, h01.y, a1);
        a2 = fmaf(ww, h23.x, a2);
        a3 = fmaf(ww, h23.y, a3);
        den += ww;
    }

    float inv = 1.0f / den;
    float4 b4 = __ldg((const float4*)bias + lane);
    float v0 = a0 * inv + b4.x;
    float v1 = a1 * inv + b4.y;
    float v2 = a2 * inv + b4.z;
    float v3 = a3 * inv + b4.w;

    float s = v0 + v1 + v2 + v3;
#pragma unroll
    for (int o = 16; o >= 1; o >>= 1) s += __shfl_xor_sync(0xffffffffu, s, o);
    float mean = s * (1.0f / 128.0f);

    float d0 = v0 - mean, d1 = v1 - mean, d2 = v2 - mean, d3 = v3 - mean;
    float q = d0 * d0 + d1 * d1 + d2 * d2 + d3 * d3;
#pragma unroll
    for (int o = 16; o >= 1; o >>= 1) q += __shfl_xor_sync(0xffffffffu, q, o);
    float r = rsqrtf(q * (1.0f / 128.0f) + LN_EPS);

    float4 g4  = __ldg((const float4*)gamma + lane);
    float4 be4 = __ldg((const float4*)beta + lane);
    float o0 = d0 * r * g4.x + be4.x;
    float o1 = d1 * r * g4.y + be4.y;
    float o2 = d2 * r * g4.z + be4.z;
    float o3 = d3 * r * g4.w + be4.w;
    o0 = o0 > 0.f ? o0 : (expf(o0) - 1.0f);
    o1 = o1 > 0.f ? o1 : (expf(o1) - 1.0f);
    o2 = o2 > 0.f ? o2 : (expf(o2) - 1.0f);
    o3 = o3 > 0.f ? o3 : (expf(o3) - 1.0f);

    *(float4*)(out + (size_t)n * HC + lane * 4) = make_float4(o0, o1, o2, o3);
}

// ---------------------------------------------------------------------------
// Launch: fork the capture stream so the CSR build (edge_index only) runs
// concurrently with prep+gemm (x, W only); join before aggr.
// Stream/events created ONCE (first call is the correctness run, outside
// capture) and reused — no per-call driver allocations.
// ---------------------------------------------------------------------------
extern "C" void kernel_launch(void* const* d_in, const int* in_sizes, int n_in,
                              void* d_out, int out_size) {
    const float* x       = (const float*)d_in[0];
    const int*   ei      = (const int*)d_in[1];
    const float* W       = (const float*)d_in[2];
    const float* att_src = (const float*)d_in[3];
    const float* att_dst = (const float*)d_in[4];
    const float* bias    = (const float*)d_in[5];
    const float* gamma   = (const float*)d_in[6];
    const float* beta    = (const float*)d_in[7];
    float*       out     = (float*)d_out;

    const int NB_SCAN1  = (N_NODES + 1023) / 1024;  // 49
    const int GEMM_SMEM = 2 * STG_BYTES;            // 60 KB dynamic

    static bool init_done = false;
    static cudaStream_t s2;
    static cudaEvent_t ev_fork, ev_join;
    if (!init_done) {
        cudaFuncSetAttribute(gemm_mma_k,
                             cudaFuncAttributeMaxDynamicSharedMemorySize, GEMM_SMEM);
        cudaStreamCreateWithFlags(&s2, cudaStreamNonBlocking);
        cudaEventCreateWithFlags(&ev_fork, cudaEventDisableTiming);
        cudaEventCreateWithFlags(&ev_join, cudaEventDisableTiming);
        init_done = true;
    }

    cudaEventRecord(ev_fork, 0);
    cudaStreamWaitEvent(s2, ev_fork, 0);

    // --- branch A (stream 0): W prep + GEMM/logits ---
    prep_k<<<(IN_DIM * HC + 255) / 256, 256>>>(W);
    gemm_mma_k<<<(N_NODES + 63) / 64, 256, GEMM_SMEM>>>(x, att_src, att_dst);

    // --- branch B (s2): CSR build ---
    zero_k<<<(N_NODES + 255) / 256, 256, 0, s2>>>();
    hist_k<<<(N_EDGES + 255) / 256, 256, 0, s2>>>(ei);
    scan1_k<<<NB_SCAN1, 1024, 0, s2>>>();
    scan2_k<<<1, 64, 0, s2>>>(NB_SCAN1);
    scan3_k<<<(N_NODES + 255) / 256, 256, 0, s2>>>();
    fill_k<<<(N_EDGES + 255) / 256, 256, 0, s2>>>(ei);
    cudaEventRecord(ev_join, s2);

    // --- join, then aggregation + LN + ELU ---
    cudaStreamWaitEvent(0, ev_join, 0);
    aggr_k<<<(N_NODES * 32 + 255) / 256, 256>>>(bias, gamma, beta, out);
}

// round 16
// speedup vs baseline: 1.1587x; 1.1587x over previous
#include <cuda_runtime.h>
#include <cuda_bf16.h>
#include <cuda_fp16.h>
#include <cstdint>

#define N_NODES 50000
#define N_EDGES 800000
#define IN_DIM  256
#define HC      128   // HEADS * OUT_DIM
#define HEADS   4
#define NEG_SLOPE 0.2f
#define LN_EPS  1e-5f

// Scratch (static device globals; no allocation at runtime)
__device__ __half g_hf[(size_t)N_NODES * HC];    // transformed features, fp16
__device__ float g_as[N_NODES * HEADS];          // alpha_src per node/head
__device__ float g_ad[N_NODES * HEADS];          // alpha_dst per node/head
// W in fp16, transposed to [n][k]
__device__ __half g_Wf[HC * IN_DIM];
// CSR-by-dst scratch
__device__ int   g_deg[N_NODES];
__device__ int   g_cur[N_NODES];
__device__ int   g_row[N_NODES + 1];
__device__ int   g_col[N_EDGES];
__device__ int   g_scan[50176];
__device__ int   g_poff[64];

// ---------------------------------------------------------------------------
// Prep (stream 0): convert W to fp16, transposed [n][k].
// ---------------------------------------------------------------------------
__global__ __launch_bounds__(256) void prep_k(const float* __restrict__ W) {
    int i = blockIdx.x * 256 + threadIdx.x;
    if (i < IN_DIM * HC) {
        int k = i >> 7, n = i & 127;
        g_Wf[n * IN_DIM + k] = __float2half_rn(W[i]);
    }
}

// CSR branch start: zero counters
__global__ __launch_bounds__(256) void zero_k() {
    int i = blockIdx.x * 256 + threadIdx.x;
    if (i < N_NODES) { g_deg[i] = 0; g_cur[i] = 0; }
}

#define MMA_F16(D, A0, A1, A2, A3, B0, B1)                                    \
    asm volatile(                                                             \
        "mma.sync.aligned.m16n8k16.row.col.f32.f16.f16.f32 "                  \
        "{%0,%1,%2,%3},{%4,%5,%6,%7},{%8,%9},{%0,%1,%2,%3};"                  \
        : "+f"(D[0]), "+f"(D[1]), "+f"(D[2]), "+f"(D[3])                      \
        : "r"(A0), "r"(A1), "r"(A2), "r"(A3), "r"(B0), "r"(B1))

#define LDSM_X4(R0, R1, R2, R3, ADDR)                                         \
    asm volatile("ldmatrix.sync.aligned.m8n8.x4.shared.b16 {%0,%1,%2,%3}, [%4];" \
                 : "=r"(R0), "=r"(R1), "=r"(R2), "=r"(R3) : "r"(ADDR))

#define CP16(dst_u32, src_ptr)                                                \
    asm volatile("cp.async.cg.shared.global [%0], [%1], 16;" ::               \
                 "r"(dst_u32), "l"(src_ptr))
#define CP_COMMIT() asm volatile("cp.async.commit_group;")
#define CP_WAIT0()  asm volatile("cp.async.wait_group 0;")

// stage layout (bytes): Xf[128][40] | Wf[128][40]  = 2*10240
#define XF_OFF 0
#define WF_OFF 10240
#define STG_BYTES 20480

// ---------------------------------------------------------------------------
// K1: h = x@W via fp16 mma (fp32 accum), double-buffered pipeline.
// Tile M=128, N=128, K-chunk 32; warp tile M=32 (2 m16), N=64 (8 n8).
// Per ks-half: 2 A-LDSM + 4 B-LDSM : 16 MMA.
// ---------------------------------------------------------------------------
__global__ __launch_bounds__(256, 2) void gemm_mma_k(const float* __restrict__ x,
                                                     const float* __restrict__ att_src,
                                                     const float* __restrict__ att_dst) {
    extern __shared__ __align__(16) char sm_raw[];

    const int tid  = threadIdx.x;
    const int wid  = tid >> 5;
    const int lane = tid & 31;
    const int g    = lane >> 2;
    const int tig  = lane & 3;
    const int wm   = (wid & 3) * 32;
    const int wn   = (wid >> 2) * 64;
    const int nb   = blockIdx.x * 128;

    const uint32_t smem_u32 = (uint32_t)__cvta_generic_to_shared(sm_raw);

    // ldmatrix per-lane byte offsets within a stage (excluding ks*2)
    int a_off[2];
#pragma unroll
    for (int mt = 0; mt < 2; mt++)
        a_off[mt] = (((wm + mt * 16 + (lane & 7) + ((lane >> 3) & 1) * 8) * 40)
                     + ((lane >> 4) & 1) * 8) * 2;
    int b_off[4];
#pragma unroll
    for (int p = 0; p < 4; p++)
        b_off[p] = (((wn + p * 16 + (lane & 7) + ((lane >> 4) & 1) * 8) * 40)
                    + ((lane >> 3) & 1) * 8) * 2;

    // X loads: 128 rows x 32 k fp32 = 1024 float4, 4 per thread
    const float* xsrc[4];
    int xoff[4];
#pragma unroll
    for (int i = 0; i < 4; i++) {
        int idx = tid + i * 256;
        int row = idx >> 3, q = idx & 7;
        int gn  = nb + row; if (gn > N_NODES - 1) gn = N_NODES - 1;
        xoff[i] = row * 40 + q * 4;
        xsrc[i] = x + (size_t)gn * IN_DIM + q * 4;
    }
    // W cp.async: 128 rows x 32 k fp16 = 8 KB per chunk = 512 CP16, 2/thread
    int wrow[2], wq[2];
#pragma unroll
    for (int i = 0; i < 2; i++) {
        int idx = tid + i * 256;
        wrow[i] = idx >> 2; wq[i] = idx & 3;
    }

    float d[2][8][4];
#pragma unroll
    for (int mt = 0; mt < 2; mt++)
#pragma unroll
        for (int nt = 0; nt < 8; nt++)
#pragma unroll
            for (int c = 0; c < 4; c++) d[mt][nt][c] = 0.f;

    float4 xs[4];

    // --- prologue: chunk 0 ---
    {
#pragma unroll
        for (int i = 0; i < 2; i++) {
            uint32_t dw = smem_u32 + WF_OFF + (wrow[i] * 40 + wq[i] * 8) * 2;
            CP16(dw, g_Wf + (size_t)wrow[i] * IN_DIM + wq[i] * 8);
        }
        CP_COMMIT();
#pragma unroll
        for (int i = 0; i < 4; i++) xs[i] = *(const float4*)(xsrc[i]);
        __half* Xf = (__half*)(sm_raw + XF_OFF);
#pragma unroll
        for (int i = 0; i < 4; i++) {
            float4 v = xs[i];
            *(__half2*)&Xf[xoff[i]]     = __floats2half2_rn(v.x, v.y);
            *(__half2*)&Xf[xoff[i] + 2] = __floats2half2_rn(v.z, v.w);
        }
        CP_WAIT0();
        __syncthreads();
    }

    for (int c = 0; c < 8; c++) {
        const int cur = c & 1;
        const int nxt = cur ^ 1;
        char* bn = sm_raw + nxt * STG_BYTES;
        const uint32_t base = smem_u32 + cur * STG_BYTES;

        if (c < 7) {
            const int kc = (c + 1) * 32;
#pragma unroll
            for (int i = 0; i < 2; i++) {
                uint32_t dw = smem_u32 + nxt * STG_BYTES + WF_OFF + (wrow[i] * 40 + wq[i] * 8) * 2;
                CP16(dw, g_Wf + (size_t)wrow[i] * IN_DIM + kc + wq[i] * 8);
            }
            CP_COMMIT();
#pragma unroll
            for (int i = 0; i < 4; i++) xs[i] = *(const float4*)(xsrc[i] + kc);
        }

        // --- compute on current stage ---
#pragma unroll
        for (int ks = 0; ks < 32; ks += 16) {
            uint32_t ah[2][4];
#pragma unroll
            for (int mt = 0; mt < 2; mt++)
                LDSM_X4(ah[mt][0], ah[mt][1], ah[mt][2], ah[mt][3],
                        base + XF_OFF + a_off[mt] + ks * 2);
#pragma unroll
            for (int p = 0; p < 4; p++) {
                uint32_t bh[4];
                LDSM_X4(bh[0], bh[1], bh[2], bh[3],
                        base + WF_OFF + b_off[p] + ks * 2);
#pragma unroll
                for (int j = 0; j < 2; j++) {
                    int nt = 2 * p + j;
#pragma unroll
                    for (int mt = 0; mt < 2; mt++)
                        MMA_F16(d[mt][nt], ah[mt][0], ah[mt][1], ah[mt][2], ah[mt][3],
                                bh[2 * j], bh[2 * j + 1]);
                }
            }
        }

        if (c < 7) {
            __half* Xfn = (__half*)(bn + XF_OFF);
#pragma unroll
            for (int i = 0; i < 4; i++) {
                float4 v = xs[i];
                *(__half2*)&Xfn[xoff[i]]     = __floats2half2_rn(v.x, v.y);
                *(__half2*)&Xfn[xoff[i] + 2] = __floats2half2_rn(v.z, v.w);
            }
            CP_WAIT0();
        }
        __syncthreads();
    }

    // ---- epilogue: store h (fp16) + attention logits (fp32) ----
    const int head0 = wn >> 5;
    float psl[2][2], pdl[2][2], psh[2][2], pdh[2][2];
#pragma unroll
    for (int mt = 0; mt < 2; mt++)
#pragma unroll
        for (int hh = 0; hh < 2; hh++) { psl[mt][hh]=pdl[mt][hh]=psh[mt][hh]=pdh[mt][hh]=0.f; }

#pragma unroll
    for (int nt = 0; nt < 8; nt++) {
        int c0 = wn + nt * 8 + 2 * tig;
        int hh = nt >> 2;
        float as0 = __ldg(att_src + c0), as1 = __ldg(att_src + c0 + 1);
        float ad0 = __ldg(att_dst + c0), ad1 = __ldg(att_dst + c0 + 1);
#pragma unroll
        for (int mt = 0; mt < 2; mt++) {
            psl[mt][hh] += d[mt][nt][0] * as0 + d[mt][nt][1] * as1;
            pdl[mt][hh] += d[mt][nt][0] * ad0 + d[mt][nt][1] * ad1;
            psh[mt][hh] += d[mt][nt][2] * as0 + d[mt][nt][3] * as1;
            pdh[mt][hh] += d[mt][nt][2] * ad0 + d[mt][nt][3] * ad1;
        }
    }
#pragma unroll
    for (int mt = 0; mt < 2; mt++)
#pragma unroll
        for (int hh = 0; hh < 2; hh++)
#pragma unroll
            for (int o = 1; o <= 2; o <<= 1) {
                psl[mt][hh] += __shfl_xor_sync(0xffffffffu, psl[mt][hh], o);
                pdl[mt][hh] += __shfl_xor_sync(0xffffffffu, pdl[mt][hh], o);
                psh[mt][hh] += __shfl_xor_sync(0xffffffffu, psh[mt][hh], o);
                pdh[mt][hh] += __shfl_xor_sync(0xffffffffu, pdh[mt][hh], o);
            }

#pragma unroll
    for (int mt = 0; mt < 2; mt++) {
        int n0 = nb + wm + mt * 16 + g;
        int n1 = n0 + 8;
        if (n0 < N_NODES) {
#pragma unroll
            for (int nt = 0; nt < 8; nt++)
                *(__half2*)(g_hf + (size_t)n0 * HC + wn + nt * 8 + 2 * tig) =
                    __floats2half2_rn(d[mt][nt][0], d[mt][nt][1]);
            if (tig == 0)
#pragma unroll
                for (int hh = 0; hh < 2; hh++) {
                    g_as[n0 * HEADS + head0 + hh] = psl[mt][hh];
                    g_ad[n0 * HEADS + head0 + hh] = pdl[mt][hh];
                }
        }
        if (n1 < N_NODES) {
#pragma unroll
            for (int nt = 0; nt < 8; nt++)
                *(__half2*)(g_hf + (size_t)n1 * HC + wn + nt * 8 + 2 * tig) =
                    __floats2half2_rn(d[mt][nt][2], d[mt][nt][3]);
            if (tig == 0)
#pragma unroll
                for (int hh = 0; hh < 2; hh++) {
                    g_as[n1 * HEADS + head0 + hh] = psh[mt][hh];
                    g_ad[n1 * HEADS + head0 + hh] = pdh[mt][hh];
                }
        }
    }
}

// ---------------------------------------------------------------------------
// CSR build: hist -> scan (2-level, warp-shuffle) -> fill
// ---------------------------------------------------------------------------
__global__ __launch_bounds__(256) void hist_k(const int* __restrict__ ei) {
    int e = blockIdx.x * 256 + threadIdx.x;
    if (e < N_EDGES) atomicAdd(&g_deg[__ldg(ei + N_EDGES + e)], 1);
}

__global__ __launch_bounds__(1024) void scan1_k() {
    __shared__ int wsum[32];
    int tid = threadIdx.x, lane = tid & 31, wid = tid >> 5;
    int i = blockIdx.x * 1024 + tid;
    int v = (i < N_NODES) ? g_deg[i] : 0;
    int s = v;
#pragma unroll
    for (int o = 1; o < 32; o <<= 1) {
        int t = __shfl_up_sync(0xffffffffu, s, o);
        if (lane >= o) s += t;
    }
    if (lane == 31) wsum[wid] = s;
    __syncthreads();
    if (wid == 0) {
        int t = wsum[lane];
#pragma unroll
        for (int o = 1; o < 32; o <<= 1) {
            int u = __shfl_up_sync(0xffffffffu, t, o);
            if (lane >= o) t += u;
        }
        wsum[lane] = t;
    }
    __syncthreads();
    if (wid > 0) s += wsum[wid - 1];
    g_scan[i] = s;
    if (tid == 1023) g_poff[blockIdx.x] = s;
}

__global__ __launch_bounds__(64) void scan2_k(int nblk) {
    __shared__ int s[64];
    int tid = threadIdx.x;
    s[tid] = (tid < nblk) ? g_poff[tid] : 0;
    __syncthreads();
    if (tid == 0) {
        int run = 0;
        for (int b = 0; b < nblk; b++) { int t = s[b]; s[b] = run; run += t; }
    }
    __syncthreads();
    if (tid < nblk) g_poff[tid] = s[tid];
}

__global__ __launch_bounds__(256) void scan3_k() {
    int i = blockIdx.x * 256 + threadIdx.x;
    if (i < N_NODES) g_row[i + 1] = g_scan[i] + g_poff[i >> 10];
    if (i == 0) g_row[0] = 0;
}

__global__ __launch_bounds__(256) void fill_k(const int* __restrict__ ei) {
    int e = blockIdx.x * 256 + threadIdx.x;
    if (e >= N_EDGES) return;
    int s = __ldg(ei + e);
    int d = __ldg(ei + N_EDGES + e);
    int pos = g_row[d] + atomicAdd(&g_cur[d], 1);
    g_col[pos] = s;
}

// ---------------------------------------------------------------------------
// Aggregation (fp16 gather, 8-way MLP unroll) fused with LayerNorm + ELU.
// One warp per dst node; lane owns 4 channels (one uint2 = 2 half2).
// ---------------------------------------------------------------------------
__global__ __launch_bounds__(256) void aggr_k(const float* __restrict__ bias,
                                              const float* __restrict__ gamma,
                                              const float* __restrict__ beta,
                                              float* __restrict__ out) {
    int gt   = blockIdx.x * 256 + threadIdx.x;
    int n    = gt >> 5;
    int lane = gt & 31;
    if (n >= N_NODES) return;
    int head = lane >> 3;

    float ad_n = __ldg(g_ad + n * HEADS + head);

    // self-loop initializes the accumulator
    float as_s = __ldg(g_as + n * HEADS + head);
    float z    = as_s + ad_n;
    float w    = __expf(z > 0.f ? z : NEG_SLOPE * z);
    uint2 u0i  = __ldg((const uint2*)(g_hf + (size_t)n * HC) + lane);
    float2 f01 = __half22float2(*(__half2*)&u0i.x);
    float2 f23 = __half22float2(*(__half2*)&u0i.y);
    float a0 = w * f01.x, a1 = w * f01.y, a2 = w * f23.x, a3 = w * f23.y;
    float den = w;

    const int e0 = __ldg(g_row + n), e1 = __ldg(g_row + n + 1);
    int i = e0;

    // --- unrolled by 8: batch independent loads to raise MLP ---
#pragma unroll 1
    for (; i + 8 <= e1; i += 8) {
        int sx[8];
        uint2 ux[8];
        float asx[8];
#pragma unroll
        for (int j = 0; j < 8; j++) sx[j] = __ldg(g_col + i + j);
#pragma unroll
        for (int j = 0; j < 8; j++)
            ux[j] = __ldg((const uint2*)(g_hf + (size_t)sx[j] * HC) + lane);
#pragma unroll
        for (int j = 0; j < 8; j++) asx[j] = __ldg(g_as + sx[j] * HEADS + head);

#pragma unroll
        for (int j = 0; j < 8; j++) {
            float zz = asx[j] + ad_n;
            float ww = __expf(zz > 0.f ? zz : NEG_SLOPE * zz);
            den += ww;
            float2 p  = __half22float2(*(__half2*)&ux[j].x);
            float2 q2 = __half22float2(*(__half2*)&ux[j].y);
            a0 = fmaf(ww, p.x, a0);  a1 = fmaf(ww, p.y, a1);
            a2 = fmaf(ww, q2.x, a2); a3 = fmaf(ww, q2.y, a3);
        }
    }
    // --- tail ---
#pragma unroll 1
    for (; i < e1; i++) {
        int s = __ldg(g_col + i);
        uint2 u  = __ldg((const uint2*)(g_hf + (size_t)s * HC) + lane);
        float as = __ldg(g_as + s * HEADS + head);
        float zz = as + ad_n;
        float ww = __expf(zz > 0.f ? zz : NEG_SLOPE * zz);
        float2 h01 = __half22float2(*(__half2*)&u.x);
        float2 h23 = __half22float2(*(__half2*)&u.y);
        a0 = fmaf(ww, h01.x, a0);
        a1 = fmaf(ww, h01.y, a1);
        a2 = fmaf(ww, h23.x, a2);
        a3 = fmaf(ww, h23.y, a3);
        den += ww;
    }

    float inv = 1.0f / den;
    float4 b4 = __ldg((const float4*)bias + lane);
    float v0 = a0 * inv + b4.x;
    float v1 = a1 * inv + b4.y;
    float v2 = a2 * inv + b4.z;
    float v3 = a3 * inv + b4.w;

    float s = v0 + v1 + v2 + v3;
#pragma unroll
    for (int o = 16; o >= 1; o >>= 1) s += __shfl_xor_sync(0xffffffffu, s, o);
    float mean = s * (1.0f / 128.0f);

    float d0 = v0 - mean, d1 = v1 - mean, d2 = v2 - mean, d3 = v3 - mean;
    float q = d0 * d0 + d1 * d1 + d2 * d2 + d3 * d3;
#pragma unroll
    for (int o = 16; o >= 1; o >>= 1) q += __shfl_xor_sync(0xffffffffu, q, o);
    float r = rsqrtf(q * (1.0f / 128.0f) + LN_EPS);

    float4 g4  = __ldg((const float4*)gamma + lane);
    float4 be4 = __ldg((const float4*)beta + lane);
    float o0 = d0 * r * g4.x + be4.x;
    float o1 = d1 * r * g4.y + be4.y;
    float o2 = d2 * r * g4.z + be4.z;
    float o3 = d3 * r * g4.w + be4.w;
    o0 = o0 > 0.f ? o0 : (expf(o0) - 1.0f);
    o1 = o1 > 0.f ? o1 : (expf(o1) - 1.0f);
    o2 = o2 > 0.f ? o2 : (expf(o2) - 1.0f);
    o3 = o3 > 0.f ? o3 : (expf(o3) - 1.0f);

    *(float4*)(out + (size_t)n * HC + lane * 4) = make_float4(o0, o1, o2, o3);
}

// ---------------------------------------------------------------------------
// Launch: fork the capture stream so the CSR build (edge_index only) runs
// concurrently with prep+gemm (x, W only); join before aggr.
// Stream/events created ONCE (first call is the correctness run, outside
// capture) and reused — no per-call driver allocations.
// ---------------------------------------------------------------------------
extern "C" void kernel_launch(void* const* d_in, const int* in_sizes, int n_in,
                              void* d_out, int out_size) {
    const float* x       = (const float*)d_in[0];
    const int*   ei      = (const int*)d_in[1];
    const float* W       = (const float*)d_in[2];
    const float* att_src = (const float*)d_in[3];
    const float* att_dst = (const float*)d_in[4];
    const float* bias    = (const float*)d_in[5];
    const float* gamma   = (const float*)d_in[6];
    const float* beta    = (const float*)d_in[7];
    float*       out     = (float*)d_out;

    const int NB_SCAN1  = (N_NODES + 1023) / 1024;  // 49
    const int GEMM_SMEM = 2 * STG_BYTES;            // 40 KB dynamic

    static bool init_done = false;
    static cudaStream_t s2;
    static cudaEvent_t ev_fork, ev_join;
    if (!init_done) {
        cudaFuncSetAttribute(gemm_mma_k,
                             cudaFuncAttributeMaxDynamicSharedMemorySize, GEMM_SMEM);
        cudaStreamCreateWithFlags(&s2, cudaStreamNonBlocking);
        cudaEventCreateWithFlags(&ev_fork, cudaEventDisableTiming);
        cudaEventCreateWithFlags(&ev_join, cudaEventDisableTiming);
        init_done = true;
    }

    cudaEventRecord(ev_fork, 0);
    cudaStreamWaitEvent(s2, ev_fork, 0);

    // --- branch A (stream 0): W prep + GEMM/logits ---
    prep_k<<<(IN_DIM * HC + 255) / 256, 256>>>(W);
    gemm_mma_k<<<(N_NODES + 127) / 128, 256, GEMM_SMEM>>>(x, att_src, att_dst);

    // --- branch B (s2): CSR build ---
    zero_k<<<(N_NODES + 255) / 256, 256, 0, s2>>>();
    hist_k<<<(N_EDGES + 255) / 256, 256, 0, s2>>>(ei);
    scan1_k<<<NB_SCAN1, 1024, 0, s2>>>();
    scan2_k<<<1, 64, 0, s2>>>(NB_SCAN1);
    scan3_k<<<(N_NODES + 255) / 256, 256, 0, s2>>>();
    fill_k<<<(N_EDGES + 255) / 256, 256, 0, s2>>>(ei);
    cudaEventRecord(ev_join, s2);

    // --- join, then aggregation + LN + ELU ---
    cudaStreamWaitEvent(0, ev_join, 0);
    aggr_k<<<(N_NODES * 32 + 255) / 256, 256>>>(bias, gamma, beta, out);
}